// round 14
// baseline (speedup 1.0000x reference)
#include <cuda_runtime.h>
#include <cuda_fp16.h>
#include <cstdint>

// Problem constants (fixed shapes)
#define DMODEL 1024
#define SEQ    2048
#define NB     4
#define MT     (NB * SEQ)   // 8192 total rows

// ---------------- scratch (device globals; no allocation allowed) -----------
__device__ unsigned short g_hIN[3][(size_t)MT * DMODEL];     // inQ,inK,inV (half)
__device__ unsigned short g_hW4[4][(size_t)DMODEL * DMODEL]; // WQ,WK,WV,WO (half)
__device__ unsigned short g_hQKV[3][(size_t)MT * DMODEL];    // projQ,K (V slot unused)
__device__ unsigned short g_hVt[(size_t)MT * DMODEL];        // V^T per batch (half)
__device__ unsigned short g_hA[(size_t)NB * SEQ * SEQ];      // attn (half)
__device__ unsigned short g_hWv[(size_t)MT * DMODEL];        // attn@V (half)
__device__ float g_S[(size_t)NB * SEQ * SEQ];                // masked scaled scores
__device__ float g_P[(size_t)MT * DMODEL];                   // out proj (fp32)

// ---------------- PTX helpers -------------------------------------------------
__device__ __forceinline__ void cp16(uint32_t saddr, const void* gptr) {
    asm volatile("cp.async.cg.shared.global [%0], [%1], 16;\n"
                 :: "r"(saddr), "l"(gptr) : "memory");
}
__device__ __forceinline__ void cp_commit() {
    asm volatile("cp.async.commit_group;\n" ::: "memory");
}
__device__ __forceinline__ void ldsm4(uint32_t* r, uint32_t addr) {
    asm volatile("ldmatrix.sync.aligned.m8n8.x4.shared.b16 {%0,%1,%2,%3}, [%4];"
                 : "=r"(r[0]), "=r"(r[1]), "=r"(r[2]), "=r"(r[3]) : "r"(addr));
}
__device__ __forceinline__ void mma16816(float* d, const uint32_t* a,
                                         uint32_t b0, uint32_t b1) {
    asm volatile(
        "mma.sync.aligned.m16n8k16.row.col.f32.f16.f16.f32 "
        "{%0,%1,%2,%3}, {%4,%5,%6,%7}, {%8,%9}, {%0,%1,%2,%3};"
        : "+f"(d[0]), "+f"(d[1]), "+f"(d[2]), "+f"(d[3])
        : "r"(a[0]), "r"(a[1]), "r"(a[2]), "r"(a[3]), "r"(b0), "r"(b1));
}

// ---------------- fp16 NT GEMM: ldmatrix + mma.sync, SW128-swizzled smem -----
// C[M,N] = A[M,K] * B^T; A [M,K], B [N,K], row-major K-major half.
// CTA tile 128x128, 4 warps with 64x64 warp tiles, BK=64, 3-stage cp.async,
// 2 CTAs/SM. Loads of the next stage are interleaved between compute steps.
// EPI: 0 = fp32 direct, 1 = fp16 staged (+ optional V^T side-write for z==2),
//      2 = mask+scale fp32 direct (scores epilogue).
constexpr int BM = 128, BN = 128, BK = 64, STG = 3;
constexpr int NTH = 128;                        // threads per CTA
constexpr int TSZ = 128 * 128;                  // bytes per (A or B) tile stage
constexpr int GSMEM = STG * 2 * TSZ;            // 98304 B; 2 CTAs fit in 228KB
constexpr int SP = 65;                          // fp32 staging stride (pad)

template <int EPI>
__global__ __launch_bounds__(NTH, 2) void gemm_h(
    const __half* __restrict__ A, const __half* __restrict__ Bm,
    void* __restrict__ Cv, const int* __restrict__ mask,
    __half* __restrict__ vt,
    int N, int K, long long sA, long long sB, long long sC)
{
    A  += (long long)blockIdx.z * sA;
    Bm += (long long)blockIdx.z * sB;

    extern __shared__ __half smh[];
    const uint32_t sbase = (uint32_t)__cvta_generic_to_shared(smh);

    const int t   = threadIdx.x;
    const int w   = t >> 5;          // 0..3
    const int ln  = t & 31;
    const int wm  = (w >> 1) * 64;   // 2 warps along M
    const int wn  = (w & 1) * 64;    // 2 warps along N
    const int bm  = blockIdx.y * BM;
    const int bn  = blockIdx.x * BN;

    // swizzled quarter-stage loader: quarter q covers chunk rows i=2q,2q+1
    // (4 cp16 per thread). Full stage = quarters 0..3, one commit.
    auto load_quarter = [&](int s, int k0, int q) {
        uint32_t ab = sbase + (uint32_t)(s * 2 * TSZ);
        uint32_t bb = ab + TSZ;
#pragma unroll
        for (int i = 2 * q; i < 2 * q + 2; i++) {
            int idx = t + i * NTH;
            int r = idx >> 3, c = idx & 7;
            uint32_t off = (uint32_t)(r * 128) + (uint32_t)(((c ^ (r & 7)) << 4));
            cp16(ab + off, &A[(long long)(bm + r) * K + k0 + c * 8]);
        }
#pragma unroll
        for (int i = 2 * q; i < 2 * q + 2; i++) {
            int idx = t + i * NTH;
            int r = idx >> 3, c = idx & 7;
            uint32_t off = (uint32_t)(r * 128) + (uint32_t)(((c ^ (r & 7)) << 4));
            cp16(bb + off, &Bm[(long long)(bn + r) * K + k0 + c * 8]);
        }
    };

    float acc[4][8][4];
#pragma unroll
    for (int i = 0; i < 4; i++)
#pragma unroll
        for (int j = 0; j < 8; j++)
#pragma unroll
            for (int e = 0; e < 4; e++) acc[i][j][e] = 0.0f;

    const int r16  = ln & 15;
    const int cbit = ln >> 4;
    const int x7   = ln & 7;

    // one K=16 step: 4 A LDSM + 4 B LDSM -> 32 mma
    auto compute_ks = [&](uint32_t aSt, uint32_t bSt, int ks) {
        const uint32_t xr = (uint32_t)(((2 * ks + cbit) ^ x7) << 4);
        uint32_t a[4][4];
#pragma unroll
        for (int mi = 0; mi < 4; mi++)
            ldsm4(a[mi], aSt + (uint32_t)((wm + mi * 16 + r16) * 128) + xr);
        uint32_t bq[4][4];
#pragma unroll
        for (int nb = 0; nb < 4; nb++)
            ldsm4(bq[nb], bSt + (uint32_t)((wn + nb * 16 + r16) * 128) + xr);
#pragma unroll
        for (int mi = 0; mi < 4; mi++)
#pragma unroll
            for (int nb = 0; nb < 4; nb++) {
                mma16816(acc[mi][2 * nb],     a[mi], bq[nb][0], bq[nb][2]);
                mma16816(acc[mi][2 * nb + 1], a[mi], bq[nb][1], bq[nb][3]);
            }
    };

    const int KT = K / BK;

#pragma unroll
    for (int s = 0; s < STG - 1; s++) {
#pragma unroll
        for (int q = 0; q < 4; q++) load_quarter(s, s * BK, q);
        cp_commit();
    }

    for (int kt = 0; kt < KT; kt++) {
        asm volatile("cp.async.wait_group 1;\n" ::: "memory");
        __syncthreads();

        const uint32_t aSt = sbase + (uint32_t)((kt % STG) * 2 * TSZ);
        const uint32_t bSt = aSt + TSZ;

        int f = kt + STG - 1;
        const bool doLoad = (f < KT);
        const int fs = f % STG;
        const int fk = f * BK;

        compute_ks(aSt, bSt, 0);
        if (doLoad) load_quarter(fs, fk, 0);
        compute_ks(aSt, bSt, 1);
        if (doLoad) load_quarter(fs, fk, 1);
        compute_ks(aSt, bSt, 2);
        if (doLoad) load_quarter(fs, fk, 2);
        compute_ks(aSt, bSt, 3);
        if (doLoad) load_quarter(fs, fk, 3);
        cp_commit();
    }

    const int fr = ln >> 2;
    const int fc = (ln & 3) * 2;

    if constexpr (EPI == 0) {
        float* Cf = (float*)Cv + (long long)blockIdx.z * sC;
#pragma unroll
        for (int mi = 0; mi < 4; mi++)
#pragma unroll
            for (int nj = 0; nj < 8; nj++) {
                long long row = bm + wm + mi * 16 + fr;
                long long col = bn + wn + nj * 8 + fc;
                float2 v0 = make_float2(acc[mi][nj][0], acc[mi][nj][1]);
                float2 v1 = make_float2(acc[mi][nj][2], acc[mi][nj][3]);
                *(float2*)&Cf[row * N + col]       = v0;
                *(float2*)&Cf[(row + 8) * N + col] = v1;
            }
    } else if constexpr (EPI == 2) {
        float* Cf = (float*)Cv + (long long)blockIdx.z * sC;
        const int* Mb = mask + (long long)blockIdx.z * sC;
#pragma unroll
        for (int mi = 0; mi < 4; mi++)
#pragma unroll
            for (int nj = 0; nj < 8; nj++) {
                long long row = bm + wm + mi * 16 + fr;
                long long col = bn + wn + nj * 8 + fc;
                long long g0 = row * N + col, g1 = (row + 8) * N + col;
                int2 m0 = *(const int2*)&Mb[g0];
                int2 m1 = *(const int2*)&Mb[g1];
                float2 v0, v1;
                v0.x = (m0.x == 1) ? -1e9f : acc[mi][nj][0] * 0.125f;
                v0.y = (m0.y == 1) ? -1e9f : acc[mi][nj][1] * 0.125f;
                v1.x = (m1.x == 1) ? -1e9f : acc[mi][nj][2] * 0.125f;
                v1.y = (m1.y == 1) ? -1e9f : acc[mi][nj][3] * 0.125f;
                *(float2*)&Cf[g0] = v0;
                *(float2*)&Cf[g1] = v1;
            }
    } else {
        // EPI == 1: stage fp32 accs in (reused) pipeline smem, 64x(64+pad)/warp
        __syncthreads();   // all warps done with LDSM reads of pipeline smem
        float* stg = (float*)smh + (size_t)w * (64 * SP);
#pragma unroll
        for (int mi = 0; mi < 4; mi++)
#pragma unroll
            for (int nj = 0; nj < 8; nj++) {
                int r0 = mi * 16 + fr, c0 = nj * 8 + fc;
                stg[r0 * SP + c0]           = acc[mi][nj][0];
                stg[r0 * SP + c0 + 1]       = acc[mi][nj][1];
                stg[(r0 + 8) * SP + c0]     = acc[mi][nj][2];
                stg[(r0 + 8) * SP + c0 + 1] = acc[mi][nj][3];
            }
        __syncwarp();
        if (vt != nullptr && blockIdx.z == 2) {
            // V^T side-write: Vt[batch][f][s] = V[s][f], coalesced half2 on s
            const int batch = bm / SEQ;
            const int sloc  = (bm % SEQ) + wm + 2 * ln;
            __half* Vtb = vt + (size_t)batch * DMODEL * SEQ;
#pragma unroll
            for (int c = 0; c < 64; c++) {
                float v0 = stg[(2 * ln) * SP + c];
                float v1 = stg[(2 * ln + 1) * SP + c];
                __half2 h = __floats2half2_rn(v0, v1);
                *(__half2*)&Vtb[(long long)(bn + wn + c) * SEQ + sloc] = h;
            }
        } else {
            __half* Ch = (__half*)Cv + (long long)blockIdx.z * sC;
#pragma unroll
            for (int it = 0; it < 64; it++) {
                float va = stg[it * SP + 2 * ln];
                float vb = stg[it * SP + 2 * ln + 1];
                __half2 h = __floats2half2_rn(va, vb);
                *(__half2*)&Ch[(long long)(bm + wm + it) * N + bn + wn + 2 * ln] = h;
            }
        }
    }
}

// ---------------- fused fp32 -> fp16 converts (ONE launch) --------------------
// y=0..2: big inputs (nBig4 float4 each). y=3: all 4 weight matrices packed
// (4*nW4 float4, consecutive). Grid x sized for the larger count.
__global__ __launch_bounds__(256) void f2h_all(
    const float* __restrict__ x0, const float* __restrict__ x1,
    const float* __restrict__ x2,
    const float* __restrict__ w0, const float* __restrict__ w1,
    const float* __restrict__ w2, const float* __restrict__ w3,
    __half* __restrict__ yIN, __half* __restrict__ yW,
    int nBig4, int nW4)
{
    int i = blockIdx.x * 256 + threadIdx.x;
    const float* x;
    __half* yo;
    if (blockIdx.y < 3) {
        if (i >= nBig4) return;
        x = (blockIdx.y == 0) ? x0 : (blockIdx.y == 1) ? x1 : x2;
        yo = yIN + (size_t)blockIdx.y * MT * DMODEL;
    } else {
        if (i >= 4 * nW4) return;
        int m = i / nW4;
        x = (m == 0) ? w0 : (m == 1) ? w1 : (m == 2) ? w2 : w3;
        x -= (size_t)m * nW4 * 4 / 1;      // adjust: index within matrix below
        // simpler: recompute local index
        x = (m == 0) ? w0 : (m == 1) ? w1 : (m == 2) ? w2 : w3;
        int il = i - m * nW4;
        float4 v = ((const float4*)x)[il];
        __half2 a = __floats2half2_rn(v.x, v.y);
        __half2 b = __floats2half2_rn(v.z, v.w);
        uint2 u; u.x = *(uint32_t*)&a; u.y = *(uint32_t*)&b;
        ((uint2*)yW)[i] = u;
        return;
    }
    float4 v = ((const float4*)x)[i];
    __half2 a = __floats2half2_rn(v.x, v.y);
    __half2 b = __floats2half2_rn(v.z, v.w);
    uint2 u; u.x = *(uint32_t*)&a; u.y = *(uint32_t*)&b;
    ((uint2*)yo)[i] = u;
}

// ---------------- softmax (max-free) over pre-masked scaled rows -> fp16 ------
// Logits are bounded (~|s| <= ~30) and masked entries are -1e9 (exp -> 0), so
// exp without max-subtraction is safe in fp32 and mathematically identical.
__global__ __launch_bounds__(256) void softmax_rows(
    const float* __restrict__ S, __half* __restrict__ Ao)
{
    const long long row = blockIdx.x;
    const float4* sr4 = (const float4*)(S + row * (long long)SEQ);
    uint2* ar2 = (uint2*)(Ao + row * (long long)SEQ);
    const int t = threadIdx.x;

    float4 q0 = sr4[t];
    float4 q1 = sr4[t + 256];
    float v[8] = {q0.x, q0.y, q0.z, q0.w, q1.x, q1.y, q1.z, q1.w};

    float sum = 0.f;
#pragma unroll
    for (int i = 0; i < 8; i++) {
        v[i] = exp2f(v[i] * 1.4426950408889634f);
        sum += v[i];
    }

    __shared__ float red[8];
#pragma unroll
    for (int o = 16; o; o >>= 1) sum += __shfl_xor_sync(~0u, sum, o);
    if ((t & 31) == 0) red[t >> 5] = sum;
    __syncthreads();
    sum = 0.f;
#pragma unroll
    for (int i = 0; i < 8; i++) sum += red[i];
    const float inv = 1.0f / sum;

    __half2 h0 = __floats2half2_rn(v[0] * inv, v[1] * inv);
    __half2 h1 = __floats2half2_rn(v[2] * inv, v[3] * inv);
    __half2 h2 = __floats2half2_rn(v[4] * inv, v[5] * inv);
    __half2 h3 = __floats2half2_rn(v[6] * inv, v[7] * inv);
    uint2 u0, u1;
    u0.x = *(uint32_t*)&h0; u0.y = *(uint32_t*)&h1;
    u1.x = *(uint32_t*)&h2; u1.y = *(uint32_t*)&h3;
    ar2[t]       = u0;
    ar2[t + 256] = u1;
}

// ---------------- residual add + LayerNorm (float4 single pass) ---------------
__global__ __launch_bounds__(256) void add_layernorm(
    const float* __restrict__ P, const float* __restrict__ R,
    const float* __restrict__ gamma, const float* __restrict__ beta,
    float* __restrict__ O)
{
    const long long row = blockIdx.x;
    const float4* pr4 = (const float4*)(P + row * (long long)DMODEL);
    const float4* rr4 = (const float4*)(R + row * (long long)DMODEL);
    float4* o4 = (float4*)(O + row * (long long)DMODEL);
    const int t = threadIdx.x;

    float4 p = pr4[t], r = rr4[t];
    float x[4] = {p.x + r.x, p.y + r.y, p.z + r.z, p.w + r.w};
    float s = x[0] + x[1] + x[2] + x[3];

    __shared__ float red[8];
#pragma unroll
    for (int o = 16; o; o >>= 1) s += __shfl_xor_sync(~0u, s, o);
    if ((t & 31) == 0) red[t >> 5] = s;
    __syncthreads();
    s = 0.f;
#pragma unroll
    for (int i = 0; i < 8; i++) s += red[i];
    const float mu = s * (1.0f / DMODEL);

    float vq = 0.f;
#pragma unroll
    for (int i = 0; i < 4; i++) {
        float d = x[i] - mu;
        vq += d * d;
    }
#pragma unroll
    for (int o = 16; o; o >>= 1) vq += __shfl_xor_sync(~0u, vq, o);
    __syncthreads();
    if ((t & 31) == 0) red[t >> 5] = vq;
    __syncthreads();
    vq = 0.f;
#pragma unroll
    for (int i = 0; i < 8; i++) vq += red[i];
    const float rs = rsqrtf(vq * (1.0f / DMODEL) + 1e-5f);

    float4 g = ((const float4*)gamma)[t];
    float4 b = ((const float4*)beta)[t];
    float4 o;
    o.x = (x[0] - mu) * rs * g.x + b.x;
    o.y = (x[1] - mu) * rs * g.y + b.y;
    o.z = (x[2] - mu) * rs * g.z + b.z;
    o.w = (x[3] - mu) * rs * g.w + b.w;
    o4[t] = o;
}

// ---------------- launch ------------------------------------------------------
extern "C" void kernel_launch(void* const* d_in, const int* in_sizes, int n_in,
                              void* d_out, int out_size)
{
    (void)in_sizes; (void)n_in; (void)out_size;
    const float* inQ  = (const float*)d_in[0];
    const float* inK  = (const float*)d_in[1];
    const float* inV  = (const float*)d_in[2];
    const int*   mask = (const int*)  d_in[3];
    const float* WQ   = (const float*)d_in[4];
    const float* WK   = (const float*)d_in[5];
    const float* WV   = (const float*)d_in[6];
    const float* WO   = (const float*)d_in[7];
    const float* gam  = (const float*)d_in[8];
    const float* bet  = (const float*)d_in[9];
    float* out = (float*)d_out;

    void *pIN, *pW4, *pQKV, *pVt, *pA, *pWv, *pS, *pP;
    cudaGetSymbolAddress(&pIN,  g_hIN);
    cudaGetSymbolAddress(&pW4,  g_hW4);
    cudaGetSymbolAddress(&pQKV, g_hQKV);
    cudaGetSymbolAddress(&pVt,  g_hVt);
    cudaGetSymbolAddress(&pA,   g_hA);
    cudaGetSymbolAddress(&pWv,  g_hWv);
    cudaGetSymbolAddress(&pS,   g_S);
    cudaGetSymbolAddress(&pP,   g_P);
    __half* hIN  = (__half*)pIN;
    __half* hW   = (__half*)pW4;
    __half* hWO  = hW + 3 * (size_t)DMODEL * DMODEL;
    __half* hQKV = (__half*)pQKV;
    __half* hQ   = hQKV;
    __half* hK   = hQKV + (size_t)MT * DMODEL;
    __half* hVt  = (__half*)pVt;
    __half* hA   = (__half*)pA;
    __half* hWv  = (__half*)pWv;
    float*  S    = (float*)pS;
    float*  P    = (float*)pP;

    cudaFuncSetAttribute(gemm_h<0>,
                         cudaFuncAttributeMaxDynamicSharedMemorySize, GSMEM);
    cudaFuncSetAttribute(gemm_h<1>,
                         cudaFuncAttributeMaxDynamicSharedMemorySize, GSMEM);
    cudaFuncSetAttribute(gemm_h<2>,
                         cudaFuncAttributeMaxDynamicSharedMemorySize, GSMEM);

    const dim3 blk(NTH);
    const long long sQK = (long long)SEQ * DMODEL;    // per-batch Q/K stride
    const long long sSS = (long long)SEQ * SEQ;       // per-batch scores stride
    const long long sVT = (long long)DMODEL * SEQ;    // per-batch V^T stride
    const long long sIN = (long long)MT * DMODEL;     // per-matrix input stride
    const long long sW  = (long long)DMODEL * DMODEL; // per-matrix weight stride

    // launch 1: ALL fp32 -> fp16 converts in one kernel
    const int nBig4 = MT * DMODEL / 4;
    const int nW4   = DMODEL * DMODEL / 4;
    f2h_all<<<dim3((nBig4 + 255) / 256, 4), 256>>>(
        inQ, inK, inV, WQ, WK, WV, WO, hIN, hW, nBig4, nW4);

    // launch 2: batched Q/K/V projections (z=0..2); z==2 writes V^T directly
    gemm_h<1><<<dim3(DMODEL / BN, MT / BM, 3), blk, GSMEM>>>(
        hIN, hW, hQKV, nullptr, hVt, DMODEL, DMODEL, sIN, sW, sIN);

    // launch 3: scores = Q*K^T with fused mask+scale -> fp32
    gemm_h<2><<<dim3(SEQ / BN, SEQ / BM, NB), blk, GSMEM>>>(
        hQ, hK, S, mask, nullptr, SEQ, DMODEL, sQK, sQK, sSS);

    // launch 4 (ncu slot): softmax (max-free) -> fp16 attn
    softmax_rows<<<NB * SEQ, 256>>>(S, hA);

    // launch 5: attn @ V = A * (V^T)^T (NT with B = V^T) -> half
    gemm_h<1><<<dim3(DMODEL / BN, SEQ / BM, NB), blk, GSMEM>>>(
        hA, hVt, hWv, nullptr, nullptr, DMODEL, SEQ, sSS, sVT, sQK);

    // launch 6: out proj: W * WO^T (NT) -> fp32
    gemm_h<0><<<dim3(DMODEL / BN, MT / BM, 1), blk, GSMEM>>>(
        hWv, hWO, P, nullptr, nullptr, DMODEL, DMODEL, 0, 0, 0);

    // launch 7: residual + layernorm -> d_out
    add_layernorm<<<MT, 256>>>(P, inQ, gam, bet, out);
}

// round 15
// speedup vs baseline: 1.0198x; 1.0198x over previous
#include <cuda_runtime.h>
#include <cuda_fp16.h>
#include <cstdint>

// Problem constants (fixed shapes)
#define DMODEL 1024
#define SEQ    2048
#define NB     4
#define MT     (NB * SEQ)   // 8192 total rows

// ---------------- scratch (device globals; no allocation allowed) -----------
__device__ unsigned short g_hIN[3][(size_t)MT * DMODEL];     // inQ,inK,inV (half)
__device__ unsigned short g_hW4[4][(size_t)DMODEL * DMODEL]; // WQ,WK,WV,WO (half)
__device__ unsigned short g_hQKV[3][(size_t)MT * DMODEL];    // projQ,K (V slot unused)
__device__ unsigned short g_hVt[(size_t)MT * DMODEL];        // V^T per batch (half)
__device__ unsigned short g_hA[(size_t)NB * SEQ * SEQ];      // attn (half)
__device__ unsigned short g_hWv[(size_t)MT * DMODEL];        // attn@V (half)
__device__ float g_S[(size_t)NB * SEQ * SEQ];                // masked scaled scores
__device__ float g_P[(size_t)MT * DMODEL];                   // out proj (fp32)

// ---------------- PTX helpers -------------------------------------------------
__device__ __forceinline__ void cp16(uint32_t saddr, const void* gptr) {
    asm volatile("cp.async.cg.shared.global [%0], [%1], 16;\n"
                 :: "r"(saddr), "l"(gptr) : "memory");
}
__device__ __forceinline__ void cp_commit() {
    asm volatile("cp.async.commit_group;\n" ::: "memory");
}
__device__ __forceinline__ void ldsm4(uint32_t* r, uint32_t addr) {
    asm volatile("ldmatrix.sync.aligned.m8n8.x4.shared.b16 {%0,%1,%2,%3}, [%4];"
                 : "=r"(r[0]), "=r"(r[1]), "=r"(r[2]), "=r"(r[3]) : "r"(addr));
}
__device__ __forceinline__ void mma16816(float* d, const uint32_t* a,
                                         uint32_t b0, uint32_t b1) {
    asm volatile(
        "mma.sync.aligned.m16n8k16.row.col.f32.f16.f16.f32 "
        "{%0,%1,%2,%3}, {%4,%5,%6,%7}, {%8,%9}, {%0,%1,%2,%3};"
        : "+f"(d[0]), "+f"(d[1]), "+f"(d[2]), "+f"(d[3])
        : "r"(a[0]), "r"(a[1]), "r"(a[2]), "r"(a[3]), "r"(b0), "r"(b1));
}

// ---------------- fp16 NT GEMM: ldmatrix + mma.sync, SW128-swizzled smem -----
// C[M,N] = A[M,K] * B^T; A [M,K], B [N,K], row-major K-major half.
// CTA tile 128x128, 4 warps with 64x64 warp tiles (each fragment loaded by
// only 2 warps -> 0.25 LDSM/MMA), BK=64, 3-stage cp.async, 2 CTAs/SM.
// EPI: 0 = fp32 direct, 1 = fp16 staged (+ optional V^T side-write for z==2),
//      2 = mask+scale fp32 direct (scores epilogue).
constexpr int BM = 128, BN = 128, BK = 64, STG = 3;
constexpr int NT = 128;                         // threads per CTA
constexpr int TSZ = 128 * 128;                  // bytes per (A or B) tile stage
constexpr int GSMEM = STG * 2 * TSZ;            // 98304 B; 2 CTAs fit in 228KB
constexpr int SP = 65;                          // fp32 staging stride (pad)

template <int EPI>
__global__ __launch_bounds__(NT, 2) void gemm_h(
    const __half* __restrict__ A, const __half* __restrict__ Bm,
    void* __restrict__ Cv, const int* __restrict__ mask,
    __half* __restrict__ vt,
    int N, int K, long long sA, long long sB, long long sC)
{
    A  += (long long)blockIdx.z * sA;
    Bm += (long long)blockIdx.z * sB;

    extern __shared__ __half smh[];
    const uint32_t sbase = (uint32_t)__cvta_generic_to_shared(smh);

    const int t   = threadIdx.x;
    const int w   = t >> 5;          // 0..3
    const int ln  = t & 31;
    const int wm  = (w >> 1) * 64;   // 2 warps along M
    const int wn  = (w & 1) * 64;    // 2 warps along N
    const int bm  = blockIdx.y * BM;
    const int bn  = blockIdx.x * BN;

    // swizzled stage loader: tile = 128 rows x 128B, chunk c (16B) at
    // r*128 + ((c ^ (r&7))<<4). 1024 chunks per tile, 8 per thread.
    auto load_stage = [&](int s, int k0) {
        uint32_t ab = sbase + (uint32_t)(s * 2 * TSZ);
        uint32_t bb = ab + TSZ;
#pragma unroll
        for (int i = 0; i < 8; i++) {
            int idx = t + i * NT;
            int r = idx >> 3, c = idx & 7;
            uint32_t off = (uint32_t)(r * 128) + (uint32_t)(((c ^ (r & 7)) << 4));
            cp16(ab + off, &A[(long long)(bm + r) * K + k0 + c * 8]);
        }
#pragma unroll
        for (int i = 0; i < 8; i++) {
            int idx = t + i * NT;
            int r = idx >> 3, c = idx & 7;
            uint32_t off = (uint32_t)(r * 128) + (uint32_t)(((c ^ (r & 7)) << 4));
            cp16(bb + off, &Bm[(long long)(bn + r) * K + k0 + c * 8]);
        }
    };

    float acc[4][8][4];
#pragma unroll
    for (int i = 0; i < 4; i++)
#pragma unroll
        for (int j = 0; j < 8; j++)
#pragma unroll
            for (int e = 0; e < 4; e++) acc[i][j][e] = 0.0f;

    const int r16  = ln & 15;
    const int cbit = ln >> 4;
    const int x7   = ln & 7;

    // one K=16 step: 4 A LDSM (64 rows) + 4 B LDSM (64 n) -> 32 mma
    auto compute_ks = [&](uint32_t aSt, uint32_t bSt, int ks) {
        const uint32_t xr = (uint32_t)(((2 * ks + cbit) ^ x7) << 4);
        uint32_t a[4][4];
#pragma unroll
        for (int mi = 0; mi < 4; mi++)
            ldsm4(a[mi], aSt + (uint32_t)((wm + mi * 16 + r16) * 128) + xr);
        uint32_t bq[4][4];
#pragma unroll
        for (int nb = 0; nb < 4; nb++)
            ldsm4(bq[nb], bSt + (uint32_t)((wn + nb * 16 + r16) * 128) + xr);
#pragma unroll
        for (int mi = 0; mi < 4; mi++)
#pragma unroll
            for (int nb = 0; nb < 4; nb++) {
                mma16816(acc[mi][2 * nb],     a[mi], bq[nb][0], bq[nb][2]);
                mma16816(acc[mi][2 * nb + 1], a[mi], bq[nb][1], bq[nb][3]);
            }
    };

    const int KT = K / BK;

#pragma unroll
    for (int s = 0; s < STG - 1; s++) { load_stage(s, s * BK); cp_commit(); }

    for (int kt = 0; kt < KT; kt++) {
        asm volatile("cp.async.wait_group 1;\n" ::: "memory");
        __syncthreads();

        const uint32_t aSt = sbase + (uint32_t)((kt % STG) * 2 * TSZ);
        const uint32_t bSt = aSt + TSZ;

        compute_ks(aSt, bSt, 0);           // tensor work first

        int f = kt + STG - 1;
        if (f < KT) load_stage(f % STG, f * BK);
        cp_commit();

        compute_ks(aSt, bSt, 1);
        compute_ks(aSt, bSt, 2);
        compute_ks(aSt, bSt, 3);
    }

    const int fr = ln >> 2;
    const int fc = (ln & 3) * 2;

    if constexpr (EPI == 0) {
        float* Cf = (float*)Cv + (long long)blockIdx.z * sC;
#pragma unroll
        for (int mi = 0; mi < 4; mi++)
#pragma unroll
            for (int nj = 0; nj < 8; nj++) {
                long long row = bm + wm + mi * 16 + fr;
                long long col = bn + wn + nj * 8 + fc;
                float2 v0 = make_float2(acc[mi][nj][0], acc[mi][nj][1]);
                float2 v1 = make_float2(acc[mi][nj][2], acc[mi][nj][3]);
                *(float2*)&Cf[row * N + col]       = v0;
                *(float2*)&Cf[(row + 8) * N + col] = v1;
            }
    } else if constexpr (EPI == 2) {
        float* Cf = (float*)Cv + (long long)blockIdx.z * sC;
        const int* Mb = mask + (long long)blockIdx.z * sC;
#pragma unroll
        for (int mi = 0; mi < 4; mi++)
#pragma unroll
            for (int nj = 0; nj < 8; nj++) {
                long long row = bm + wm + mi * 16 + fr;
                long long col = bn + wn + nj * 8 + fc;
                long long g0 = row * N + col, g1 = (row + 8) * N + col;
                int2 m0 = *(const int2*)&Mb[g0];
                int2 m1 = *(const int2*)&Mb[g1];
                float2 v0, v1;
                v0.x = (m0.x == 1) ? -1e9f : acc[mi][nj][0] * 0.125f;
                v0.y = (m0.y == 1) ? -1e9f : acc[mi][nj][1] * 0.125f;
                v1.x = (m1.x == 1) ? -1e9f : acc[mi][nj][2] * 0.125f;
                v1.y = (m1.y == 1) ? -1e9f : acc[mi][nj][3] * 0.125f;
                *(float2*)&Cf[g0] = v0;
                *(float2*)&Cf[g1] = v1;
            }
    } else {
        // EPI == 1: stage fp32 accs in (reused) pipeline smem, 64x(64+pad)/warp
        __syncthreads();   // all warps done with LDSM reads of pipeline smem
        float* stg = (float*)smh + (size_t)w * (64 * SP);
#pragma unroll
        for (int mi = 0; mi < 4; mi++)
#pragma unroll
            for (int nj = 0; nj < 8; nj++) {
                int r0 = mi * 16 + fr, c0 = nj * 8 + fc;
                stg[r0 * SP + c0]           = acc[mi][nj][0];
                stg[r0 * SP + c0 + 1]       = acc[mi][nj][1];
                stg[(r0 + 8) * SP + c0]     = acc[mi][nj][2];
                stg[(r0 + 8) * SP + c0 + 1] = acc[mi][nj][3];
            }
        __syncwarp();
        if (vt != nullptr && blockIdx.z == 2) {
            // V^T side-write: Vt[batch][f][s] = V[s][f], coalesced half2 on s
            const int batch = bm / SEQ;
            const int sloc  = (bm % SEQ) + wm + 2 * ln;
            __half* Vtb = vt + (size_t)batch * DMODEL * SEQ;
#pragma unroll
            for (int c = 0; c < 64; c++) {
                float v0 = stg[(2 * ln) * SP + c];
                float v1 = stg[(2 * ln + 1) * SP + c];
                __half2 h = __floats2half2_rn(v0, v1);
                *(__half2*)&Vtb[(long long)(bn + wn + c) * SEQ + sloc] = h;
            }
        } else {
            __half* Ch = (__half*)Cv + (long long)blockIdx.z * sC;
#pragma unroll
            for (int it = 0; it < 64; it++) {
                float va = stg[it * SP + 2 * ln];
                float vb = stg[it * SP + 2 * ln + 1];
                __half2 h = __floats2half2_rn(va, vb);
                *(__half2*)&Ch[(long long)(bm + wm + it) * N + bn + wn + 2 * ln] = h;
            }
        }
    }
}

// ---------------- fused fp32 -> fp16 converts ---------------------------------
__global__ __launch_bounds__(256) void f2h3(
    const float* __restrict__ x0, const float* __restrict__ x1,
    const float* __restrict__ x2, __half* __restrict__ y, int n4)
{
    const float* x = (blockIdx.y == 0) ? x0 : (blockIdx.y == 1) ? x1 : x2;
    __half* yo = y + (size_t)blockIdx.y * MT * DMODEL;
    int i = blockIdx.x * 256 + threadIdx.x;
    if (i < n4) {
        float4 v = ((const float4*)x)[i];
        __half2 a = __floats2half2_rn(v.x, v.y);
        __half2 b = __floats2half2_rn(v.z, v.w);
        uint2 u; u.x = *(uint32_t*)&a; u.y = *(uint32_t*)&b;
        ((uint2*)yo)[i] = u;
    }
}

__global__ __launch_bounds__(256) void f2h4(
    const float* __restrict__ x0, const float* __restrict__ x1,
    const float* __restrict__ x2, const float* __restrict__ x3,
    __half* __restrict__ y, int n4)
{
    const float* x = (blockIdx.y == 0) ? x0 : (blockIdx.y == 1) ? x1
                   : (blockIdx.y == 2) ? x2 : x3;
    __half* yo = y + (size_t)blockIdx.y * DMODEL * DMODEL;
    int i = blockIdx.x * 256 + threadIdx.x;
    if (i < n4) {
        float4 v = ((const float4*)x)[i];
        __half2 a = __floats2half2_rn(v.x, v.y);
        __half2 b = __floats2half2_rn(v.z, v.w);
        uint2 u; u.x = *(uint32_t*)&a; u.y = *(uint32_t*)&b;
        ((uint2*)yo)[i] = u;
    }
}

// ---------------- softmax (max-free) over pre-masked scaled rows -> fp16 ------
// Logits are bounded (|s| <= ~30 unmasked; masked = -1e9 -> exp = 0), so exp
// without max-subtraction is safe in fp32 and mathematically identical.
__global__ __launch_bounds__(256) void softmax_rows(
    const float* __restrict__ S, __half* __restrict__ Ao)
{
    const long long row = blockIdx.x;
    const float4* sr4 = (const float4*)(S + row * (long long)SEQ);
    uint2* ar2 = (uint2*)(Ao + row * (long long)SEQ);
    const int t = threadIdx.x;

    float4 q0 = sr4[t];
    float4 q1 = sr4[t + 256];
    float v[8] = {q0.x, q0.y, q0.z, q0.w, q1.x, q1.y, q1.z, q1.w};

    float sum = 0.f;
#pragma unroll
    for (int i = 0; i < 8; i++) {
        v[i] = exp2f(v[i] * 1.4426950408889634f);
        sum += v[i];
    }

    __shared__ float red[8];
#pragma unroll
    for (int o = 16; o; o >>= 1) sum += __shfl_xor_sync(~0u, sum, o);
    if ((t & 31) == 0) red[t >> 5] = sum;
    __syncthreads();
    sum = 0.f;
#pragma unroll
    for (int i = 0; i < 8; i++) sum += red[i];
    const float inv = 1.0f / sum;

    __half2 h0 = __floats2half2_rn(v[0] * inv, v[1] * inv);
    __half2 h1 = __floats2half2_rn(v[2] * inv, v[3] * inv);
    __half2 h2 = __floats2half2_rn(v[4] * inv, v[5] * inv);
    __half2 h3 = __floats2half2_rn(v[6] * inv, v[7] * inv);
    uint2 u0, u1;
    u0.x = *(uint32_t*)&h0; u0.y = *(uint32_t*)&h1;
    u1.x = *(uint32_t*)&h2; u1.y = *(uint32_t*)&h3;
    ar2[t]       = u0;
    ar2[t + 256] = u1;
}

// ---------------- residual add + LayerNorm (float4 single pass) ---------------
__global__ __launch_bounds__(256) void add_layernorm(
    const float* __restrict__ P, const float* __restrict__ R,
    const float* __restrict__ gamma, const float* __restrict__ beta,
    float* __restrict__ O)
{
    const long long row = blockIdx.x;
    const float4* pr4 = (const float4*)(P + row * (long long)DMODEL);
    const float4* rr4 = (const float4*)(R + row * (long long)DMODEL);
    float4* o4 = (float4*)(O + row * (long long)DMODEL);
    const int t = threadIdx.x;

    float4 p = pr4[t], r = rr4[t];
    float x[4] = {p.x + r.x, p.y + r.y, p.z + r.z, p.w + r.w};
    float s = x[0] + x[1] + x[2] + x[3];

    __shared__ float red[8];
#pragma unroll
    for (int o = 16; o; o >>= 1) s += __shfl_xor_sync(~0u, s, o);
    if ((t & 31) == 0) red[t >> 5] = s;
    __syncthreads();
    s = 0.f;
#pragma unroll
    for (int i = 0; i < 8; i++) s += red[i];
    const float mu = s * (1.0f / DMODEL);

    float vq = 0.f;
#pragma unroll
    for (int i = 0; i < 4; i++) {
        float d = x[i] - mu;
        vq += d * d;
    }
#pragma unroll
    for (int o = 16; o; o >>= 1) vq += __shfl_xor_sync(~0u, vq, o);
    __syncthreads();
    if ((t & 31) == 0) red[t >> 5] = vq;
    __syncthreads();
    vq = 0.f;
#pragma unroll
    for (int i = 0; i < 8; i++) vq += red[i];
    const float rs = rsqrtf(vq * (1.0f / DMODEL) + 1e-5f);

    float4 g = ((const float4*)gamma)[t];
    float4 b = ((const float4*)beta)[t];
    float4 o;
    o.x = (x[0] - mu) * rs * g.x + b.x;
    o.y = (x[1] - mu) * rs * g.y + b.y;
    o.z = (x[2] - mu) * rs * g.z + b.z;
    o.w = (x[3] - mu) * rs * g.w + b.w;
    o4[t] = o;
}

// ---------------- launch ------------------------------------------------------
extern "C" void kernel_launch(void* const* d_in, const int* in_sizes, int n_in,
                              void* d_out, int out_size)
{
    (void)in_sizes; (void)n_in; (void)out_size;
    const float* inQ  = (const float*)d_in[0];
    const float* inK  = (const float*)d_in[1];
    const float* inV  = (const float*)d_in[2];
    const int*   mask = (const int*)  d_in[3];
    const float* WQ   = (const float*)d_in[4];
    const float* WK   = (const float*)d_in[5];
    const float* WV   = (const float*)d_in[6];
    const float* WO   = (const float*)d_in[7];
    const float* gam  = (const float*)d_in[8];
    const float* bet  = (const float*)d_in[9];
    float* out = (float*)d_out;

    void *pIN, *pW4, *pQKV, *pVt, *pA, *pWv, *pS, *pP;
    cudaGetSymbolAddress(&pIN,  g_hIN);
    cudaGetSymbolAddress(&pW4,  g_hW4);
    cudaGetSymbolAddress(&pQKV, g_hQKV);
    cudaGetSymbolAddress(&pVt,  g_hVt);
    cudaGetSymbolAddress(&pA,   g_hA);
    cudaGetSymbolAddress(&pWv,  g_hWv);
    cudaGetSymbolAddress(&pS,   g_S);
    cudaGetSymbolAddress(&pP,   g_P);
    __half* hIN  = (__half*)pIN;
    __half* hW   = (__half*)pW4;
    __half* hWO  = hW + 3 * (size_t)DMODEL * DMODEL;
    __half* hQKV = (__half*)pQKV;
    __half* hQ   = hQKV;
    __half* hK   = hQKV + (size_t)MT * DMODEL;
    __half* hVt  = (__half*)pVt;
    __half* hA   = (__half*)pA;
    __half* hWv  = (__half*)pWv;
    float*  S    = (float*)pS;
    float*  P    = (float*)pP;

    cudaFuncSetAttribute(gemm_h<0>,
                         cudaFuncAttributeMaxDynamicSharedMemorySize, GSMEM);
    cudaFuncSetAttribute(gemm_h<1>,
                         cudaFuncAttributeMaxDynamicSharedMemorySize, GSMEM);
    cudaFuncSetAttribute(gemm_h<2>,
                         cudaFuncAttributeMaxDynamicSharedMemorySize, GSMEM);

    const dim3 blk(NT);
    const long long sQK = (long long)SEQ * DMODEL;    // per-batch Q/K stride
    const long long sSS = (long long)SEQ * SEQ;       // per-batch scores stride
    const long long sVT = (long long)DMODEL * SEQ;    // per-batch V^T stride
    const long long sIN = (long long)MT * DMODEL;     // per-matrix input stride
    const long long sW  = (long long)DMODEL * DMODEL; // per-matrix weight stride

    // launch 1-2: fused fp32 -> fp16 converts
    const int nBig4 = MT * DMODEL / 4;
    const int nW4   = DMODEL * DMODEL / 4;
    f2h3<<<dim3((nBig4 + 255) / 256, 3), 256>>>(inQ, inK, inV, hIN, nBig4);
    f2h4<<<dim3((nW4 + 255) / 256, 4), 256>>>(WQ, WK, WV, WO, hW, nW4);

    // launch 3: batched Q/K/V projections (z=0..2); z==2 writes V^T directly
    gemm_h<1><<<dim3(DMODEL / BN, MT / BM, 3), blk, GSMEM>>>(
        hIN, hW, hQKV, nullptr, hVt, DMODEL, DMODEL, sIN, sW, sIN);

    // launch 4: scores = Q*K^T with fused mask+scale -> fp32
    gemm_h<2><<<dim3(SEQ / BN, SEQ / BM, NB), blk, GSMEM>>>(
        hQ, hK, S, mask, nullptr, SEQ, DMODEL, sQK, sQK, sSS);

    // launch 5: softmax (max-free) -> fp16 attn
    softmax_rows<<<NB * SEQ, 256>>>(S, hA);

    // launch 6: attn @ V = A * (V^T)^T (NT with B = V^T) -> half
    gemm_h<1><<<dim3(DMODEL / BN, SEQ / BM, NB), blk, GSMEM>>>(
        hA, hVt, hWv, nullptr, nullptr, DMODEL, SEQ, sSS, sVT, sQK);

    // launch 7: out proj: W * WO^T (NT) -> fp32
    gemm_h<0><<<dim3(DMODEL / BN, MT / BM, 1), blk, GSMEM>>>(
        hWv, hWO, P, nullptr, nullptr, DMODEL, DMODEL, 0, 0, 0);

    // launch 8: residual + layernorm -> d_out
    add_layernorm<<<MT, 256>>>(P, inQ, gam, bet, out);
}

// round 16
// speedup vs baseline: 1.2591x; 1.2346x over previous
#include <cuda_runtime.h>
#include <cuda_fp16.h>
#include <cstdint>

// Problem constants (fixed shapes)
#define DMODEL 1024
#define SEQ    2048
#define NB     4
#define MT     (NB * SEQ)   // 8192 total rows
#define WSZ    ((size_t)DMODEL * DMODEL)

// ---------------- scratch (device globals; no allocation allowed) -----------
__device__ unsigned short g_hIN[3][(size_t)MT * DMODEL];   // inQ,inK,inV (half)
// TT slots: [0]=WO [1]=WKt [2]=WVt [3]=WQt [4]=WVO=WO@WV [5]=Bqg=WK^T@WQ
__device__ unsigned short g_hTT[6][WSZ];
__device__ unsigned short g_hQg[(size_t)MT * DMODEL];      // Qg = inQ @ Bqg^T
__device__ unsigned short g_hVt[(size_t)MT * DMODEL];      // VO^T per batch
__device__ unsigned short g_hA[(size_t)NB * SEQ * SEQ];    // attn (half)
__device__ float g_S[(size_t)NB * SEQ * SEQ];              // masked scaled scores
__device__ float g_P[(size_t)MT * DMODEL];                 // attn@VO = out proj

// ---------------- PTX helpers -------------------------------------------------
__device__ __forceinline__ void cp16(uint32_t saddr, const void* gptr) {
    asm volatile("cp.async.cg.shared.global [%0], [%1], 16;\n"
                 :: "r"(saddr), "l"(gptr) : "memory");
}
__device__ __forceinline__ void cp_commit() {
    asm volatile("cp.async.commit_group;\n" ::: "memory");
}
__device__ __forceinline__ void ldsm4(uint32_t* r, uint32_t addr) {
    asm volatile("ldmatrix.sync.aligned.m8n8.x4.shared.b16 {%0,%1,%2,%3}, [%4];"
                 : "=r"(r[0]), "=r"(r[1]), "=r"(r[2]), "=r"(r[3]) : "r"(addr));
}
__device__ __forceinline__ void mma16816(float* d, const uint32_t* a,
                                         uint32_t b0, uint32_t b1) {
    asm volatile(
        "mma.sync.aligned.m16n8k16.row.col.f32.f16.f16.f32 "
        "{%0,%1,%2,%3}, {%4,%5,%6,%7}, {%8,%9}, {%0,%1,%2,%3};"
        : "+f"(d[0]), "+f"(d[1]), "+f"(d[2]), "+f"(d[3])
        : "r"(a[0]), "r"(a[1]), "r"(a[2]), "r"(a[3]), "r"(b0), "r"(b1));
}

// ---------------- fp16 NT GEMM: ldmatrix + mma.sync, SW128-swizzled smem -----
// C[M,N] = A[M,K] * B^T; A [M,K], B [N,K], row-major K-major half.
// CTA tile 128x128, 4 warps with 64x64 warp tiles, BK=64, 3-stage cp.async,
// 2 CTAs/SM. EPI: 0 = fp32 direct, 1 = fp16 staged (+ V^T side-write when
// vt!=null && z==1), 2 = mask+scale fp32 direct (scores epilogue).
constexpr int BM = 128, BN = 128, BK = 64, STG = 3;
constexpr int NT = 128;                         // threads per CTA
constexpr int TSZ = 128 * 128;                  // bytes per (A or B) tile stage
constexpr int GSMEM = STG * 2 * TSZ;            // 98304 B; 2 CTAs fit in 228KB
constexpr int SP = 65;                          // fp32 staging stride (pad)

template <int EPI>
__global__ __launch_bounds__(NT, 2) void gemm_h(
    const __half* __restrict__ A, const __half* __restrict__ Bm,
    void* __restrict__ Cv, const int* __restrict__ mask,
    __half* __restrict__ vt,
    int N, int K, long long sA, long long sB, long long sC)
{
    A  += (long long)blockIdx.z * sA;
    Bm += (long long)blockIdx.z * sB;

    extern __shared__ __half smh[];
    const uint32_t sbase = (uint32_t)__cvta_generic_to_shared(smh);

    const int t   = threadIdx.x;
    const int w   = t >> 5;          // 0..3
    const int ln  = t & 31;
    const int wm  = (w >> 1) * 64;   // 2 warps along M
    const int wn  = (w & 1) * 64;    // 2 warps along N
    const int bm  = blockIdx.y * BM;
    const int bn  = blockIdx.x * BN;

    auto load_stage = [&](int s, int k0) {
        uint32_t ab = sbase + (uint32_t)(s * 2 * TSZ);
        uint32_t bb = ab + TSZ;
#pragma unroll
        for (int i = 0; i < 8; i++) {
            int idx = t + i * NT;
            int r = idx >> 3, c = idx & 7;
            uint32_t off = (uint32_t)(r * 128) + (uint32_t)(((c ^ (r & 7)) << 4));
            cp16(ab + off, &A[(long long)(bm + r) * K + k0 + c * 8]);
        }
#pragma unroll
        for (int i = 0; i < 8; i++) {
            int idx = t + i * NT;
            int r = idx >> 3, c = idx & 7;
            uint32_t off = (uint32_t)(r * 128) + (uint32_t)(((c ^ (r & 7)) << 4));
            cp16(bb + off, &Bm[(long long)(bn + r) * K + k0 + c * 8]);
        }
    };

    float acc[4][8][4];
#pragma unroll
    for (int i = 0; i < 4; i++)
#pragma unroll
        for (int j = 0; j < 8; j++)
#pragma unroll
            for (int e = 0; e < 4; e++) acc[i][j][e] = 0.0f;

    const int r16  = ln & 15;
    const int cbit = ln >> 4;
    const int x7   = ln & 7;

    auto compute_ks = [&](uint32_t aSt, uint32_t bSt, int ks) {
        const uint32_t xr = (uint32_t)(((2 * ks + cbit) ^ x7) << 4);
        uint32_t a[4][4];
#pragma unroll
        for (int mi = 0; mi < 4; mi++)
            ldsm4(a[mi], aSt + (uint32_t)((wm + mi * 16 + r16) * 128) + xr);
        uint32_t bq[4][4];
#pragma unroll
        for (int nb = 0; nb < 4; nb++)
            ldsm4(bq[nb], bSt + (uint32_t)((wn + nb * 16 + r16) * 128) + xr);
#pragma unroll
        for (int mi = 0; mi < 4; mi++)
#pragma unroll
            for (int nb = 0; nb < 4; nb++) {
                mma16816(acc[mi][2 * nb],     a[mi], bq[nb][0], bq[nb][2]);
                mma16816(acc[mi][2 * nb + 1], a[mi], bq[nb][1], bq[nb][3]);
            }
    };

    const int KT = K / BK;

#pragma unroll
    for (int s = 0; s < STG - 1; s++) { load_stage(s, s * BK); cp_commit(); }

    for (int kt = 0; kt < KT; kt++) {
        asm volatile("cp.async.wait_group 1;\n" ::: "memory");
        __syncthreads();

        const uint32_t aSt = sbase + (uint32_t)((kt % STG) * 2 * TSZ);
        const uint32_t bSt = aSt + TSZ;

        compute_ks(aSt, bSt, 0);           // tensor work first

        int f = kt + STG - 1;
        if (f < KT) load_stage(f % STG, f * BK);
        cp_commit();

        compute_ks(aSt, bSt, 1);
        compute_ks(aSt, bSt, 2);
        compute_ks(aSt, bSt, 3);
    }

    const int fr = ln >> 2;
    const int fc = (ln & 3) * 2;

    if constexpr (EPI == 0) {
        float* Cf = (float*)Cv + (long long)blockIdx.z * sC;
#pragma unroll
        for (int mi = 0; mi < 4; mi++)
#pragma unroll
            for (int nj = 0; nj < 8; nj++) {
                long long row = bm + wm + mi * 16 + fr;
                long long col = bn + wn + nj * 8 + fc;
                float2 v0 = make_float2(acc[mi][nj][0], acc[mi][nj][1]);
                float2 v1 = make_float2(acc[mi][nj][2], acc[mi][nj][3]);
                *(float2*)&Cf[row * N + col]       = v0;
                *(float2*)&Cf[(row + 8) * N + col] = v1;
            }
    } else if constexpr (EPI == 2) {
        float* Cf = (float*)Cv + (long long)blockIdx.z * sC;
        const int* Mb = mask + (long long)blockIdx.z * sC;
#pragma unroll
        for (int mi = 0; mi < 4; mi++)
#pragma unroll
            for (int nj = 0; nj < 8; nj++) {
                long long row = bm + wm + mi * 16 + fr;
                long long col = bn + wn + nj * 8 + fc;
                long long g0 = row * N + col, g1 = (row + 8) * N + col;
                int2 m0 = *(const int2*)&Mb[g0];
                int2 m1 = *(const int2*)&Mb[g1];
                float2 v0, v1;
                v0.x = (m0.x == 1) ? -1e9f : acc[mi][nj][0] * 0.125f;
                v0.y = (m0.y == 1) ? -1e9f : acc[mi][nj][1] * 0.125f;
                v1.x = (m1.x == 1) ? -1e9f : acc[mi][nj][2] * 0.125f;
                v1.y = (m1.y == 1) ? -1e9f : acc[mi][nj][3] * 0.125f;
                *(float2*)&Cf[g0] = v0;
                *(float2*)&Cf[g1] = v1;
            }
    } else {
        // EPI == 1: stage fp32 accs in (reused) pipeline smem, 64x(64+pad)/warp
        __syncthreads();   // all warps done with LDSM reads of pipeline smem
        float* stg = (float*)smh + (size_t)w * (64 * SP);
#pragma unroll
        for (int mi = 0; mi < 4; mi++)
#pragma unroll
            for (int nj = 0; nj < 8; nj++) {
                int r0 = mi * 16 + fr, c0 = nj * 8 + fc;
                stg[r0 * SP + c0]           = acc[mi][nj][0];
                stg[r0 * SP + c0 + 1]       = acc[mi][nj][1];
                stg[(r0 + 8) * SP + c0]     = acc[mi][nj][2];
                stg[(r0 + 8) * SP + c0 + 1] = acc[mi][nj][3];
            }
        __syncwarp();
        if (vt != nullptr && blockIdx.z == 1) {
            // VO^T side-write: Vt[batch][f][s] = VO[s][f], coalesced half2 on s
            const int batch = bm / SEQ;
            const int sloc  = (bm % SEQ) + wm + 2 * ln;
            __half* Vtb = vt + (size_t)batch * DMODEL * SEQ;
#pragma unroll
            for (int c = 0; c < 64; c++) {
                float v0 = stg[(2 * ln) * SP + c];
                float v1 = stg[(2 * ln + 1) * SP + c];
                __half2 h = __floats2half2_rn(v0, v1);
                *(__half2*)&Vtb[(long long)(bn + wn + c) * SEQ + sloc] = h;
            }
        } else {
            __half* Ch = (__half*)Cv + (long long)blockIdx.z * sC;
#pragma unroll
            for (int it = 0; it < 64; it++) {
                float va = stg[it * SP + 2 * ln];
                float vb = stg[it * SP + 2 * ln + 1];
                __half2 h = __floats2half2_rn(va, vb);
                *(__half2*)&Ch[(long long)(bm + wm + it) * N + bn + wn + 2 * ln] = h;
            }
        }
    }
}

// ---------------- input fp32 -> fp16 converts ---------------------------------
__global__ __launch_bounds__(256) void f2h3(
    const float* __restrict__ x0, const float* __restrict__ x1,
    const float* __restrict__ x2, __half* __restrict__ y, int n4)
{
    const float* x = (blockIdx.y == 0) ? x0 : (blockIdx.y == 1) ? x1 : x2;
    __half* yo = y + (size_t)blockIdx.y * MT * DMODEL;
    int i = blockIdx.x * 256 + threadIdx.x;
    if (i < n4) {
        float4 v = ((const float4*)x)[i];
        __half2 a = __floats2half2_rn(v.x, v.y);
        __half2 b = __floats2half2_rn(v.z, v.w);
        uint2 u; u.x = *(uint32_t*)&a; u.y = *(uint32_t*)&b;
        ((uint2*)yo)[i] = u;
    }
}

// ---------------- weight prep: transposed-converts + WO copy ------------------
// z=0: WK -> TT[1] transposed; z=1: WV -> TT[2] transposed;
// z=2: WQ -> TT[3] transposed; z=3: WO -> TT[0] straight convert.
__global__ __launch_bounds__(256) void prep_w(
    const float* __restrict__ WQ, const float* __restrict__ WK,
    const float* __restrict__ WV, const float* __restrict__ WO,
    __half* __restrict__ TT)
{
    const int z  = blockIdx.z;
    const int c0 = blockIdx.x * 32, r0 = blockIdx.y * 32;
    const int tx = threadIdx.x & 31, ty = (threadIdx.x >> 5) * 4;

    if (z == 3) {
        __half* dst = TT;   // slot 0
#pragma unroll
        for (int i = 0; i < 4; i++)
            dst[(size_t)(r0 + ty + i) * DMODEL + c0 + tx] =
                __float2half_rn(WO[(size_t)(r0 + ty + i) * DMODEL + c0 + tx]);
        return;
    }
    __shared__ float tile[32][33];
    const float* src = (z == 0) ? WK : (z == 1) ? WV : WQ;
    __half* dst = TT + (size_t)(z + 1) * WSZ;   // slots 1,2,3
#pragma unroll
    for (int i = 0; i < 4; i++)
        tile[ty + i][tx] = src[(size_t)(r0 + ty + i) * DMODEL + c0 + tx];
    __syncthreads();
#pragma unroll
    for (int i = 0; i < 4; i++)
        dst[(size_t)(c0 + ty + i) * DMODEL + r0 + tx] =
            __float2half_rn(tile[tx][ty + i]);
}

// ---------------- softmax (max-free) over pre-masked scaled rows -> fp16 ------
__global__ __launch_bounds__(256) void softmax_rows(
    const float* __restrict__ S, __half* __restrict__ Ao)
{
    const long long row = blockIdx.x;
    const float4* sr4 = (const float4*)(S + row * (long long)SEQ);
    uint2* ar2 = (uint2*)(Ao + row * (long long)SEQ);
    const int t = threadIdx.x;

    float4 q0 = sr4[t];
    float4 q1 = sr4[t + 256];
    float v[8] = {q0.x, q0.y, q0.z, q0.w, q1.x, q1.y, q1.z, q1.w};

    float sum = 0.f;
#pragma unroll
    for (int i = 0; i < 8; i++) {
        v[i] = exp2f(v[i] * 1.4426950408889634f);
        sum += v[i];
    }

    __shared__ float red[8];
#pragma unroll
    for (int o = 16; o; o >>= 1) sum += __shfl_xor_sync(~0u, sum, o);
    if ((t & 31) == 0) red[t >> 5] = sum;
    __syncthreads();
    sum = 0.f;
#pragma unroll
    for (int i = 0; i < 8; i++) sum += red[i];
    const float inv = 1.0f / sum;

    __half2 h0 = __floats2half2_rn(v[0] * inv, v[1] * inv);
    __half2 h1 = __floats2half2_rn(v[2] * inv, v[3] * inv);
    __half2 h2 = __floats2half2_rn(v[4] * inv, v[5] * inv);
    __half2 h3 = __floats2half2_rn(v[6] * inv, v[7] * inv);
    uint2 u0, u1;
    u0.x = *(uint32_t*)&h0; u0.y = *(uint32_t*)&h1;
    u1.x = *(uint32_t*)&h2; u1.y = *(uint32_t*)&h3;
    ar2[t]       = u0;
    ar2[t + 256] = u1;
}

// ---------------- residual add + LayerNorm (float4 single pass) ---------------
__global__ __launch_bounds__(256) void add_layernorm(
    const float* __restrict__ P, const float* __restrict__ R,
    const float* __restrict__ gamma, const float* __restrict__ beta,
    float* __restrict__ O)
{
    const long long row = blockIdx.x;
    const float4* pr4 = (const float4*)(P + row * (long long)DMODEL);
    const float4* rr4 = (const float4*)(R + row * (long long)DMODEL);
    float4* o4 = (float4*)(O + row * (long long)DMODEL);
    const int t = threadIdx.x;

    float4 p = pr4[t], r = rr4[t];
    float x[4] = {p.x + r.x, p.y + r.y, p.z + r.z, p.w + r.w};
    float s = x[0] + x[1] + x[2] + x[3];

    __shared__ float red[8];
#pragma unroll
    for (int o = 16; o; o >>= 1) s += __shfl_xor_sync(~0u, s, o);
    if ((t & 31) == 0) red[t >> 5] = s;
    __syncthreads();
    s = 0.f;
#pragma unroll
    for (int i = 0; i < 8; i++) s += red[i];
    const float mu = s * (1.0f / DMODEL);

    float vq = 0.f;
#pragma unroll
    for (int i = 0; i < 4; i++) {
        float d = x[i] - mu;
        vq += d * d;
    }
#pragma unroll
    for (int o = 16; o; o >>= 1) vq += __shfl_xor_sync(~0u, vq, o);
    __syncthreads();
    if ((t & 31) == 0) red[t >> 5] = vq;
    __syncthreads();
    vq = 0.f;
#pragma unroll
    for (int i = 0; i < 8; i++) vq += red[i];
    const float rs = rsqrtf(vq * (1.0f / DMODEL) + 1e-5f);

    float4 g = ((const float4*)gamma)[t];
    float4 b = ((const float4*)beta)[t];
    float4 o;
    o.x = (x[0] - mu) * rs * g.x + b.x;
    o.y = (x[1] - mu) * rs * g.y + b.y;
    o.z = (x[2] - mu) * rs * g.z + b.z;
    o.w = (x[3] - mu) * rs * g.w + b.w;
    o4[t] = o;
}

// ---------------- launch ------------------------------------------------------
extern "C" void kernel_launch(void* const* d_in, const int* in_sizes, int n_in,
                              void* d_out, int out_size)
{
    (void)in_sizes; (void)n_in; (void)out_size;
    const float* inQ  = (const float*)d_in[0];
    const float* inK  = (const float*)d_in[1];
    const float* inV  = (const float*)d_in[2];
    const int*   mask = (const int*)  d_in[3];
    const float* WQ   = (const float*)d_in[4];
    const float* WK   = (const float*)d_in[5];
    const float* WV   = (const float*)d_in[6];
    const float* WO   = (const float*)d_in[7];
    const float* gam  = (const float*)d_in[8];
    const float* bet  = (const float*)d_in[9];
    float* out = (float*)d_out;

    void *pIN, *pTT, *pQg, *pVt, *pA, *pS, *pP;
    cudaGetSymbolAddress(&pIN, g_hIN);
    cudaGetSymbolAddress(&pTT, g_hTT);
    cudaGetSymbolAddress(&pQg, g_hQg);
    cudaGetSymbolAddress(&pVt, g_hVt);
    cudaGetSymbolAddress(&pA,  g_hA);
    cudaGetSymbolAddress(&pS,  g_S);
    cudaGetSymbolAddress(&pP,  g_P);
    __half* hIN  = (__half*)pIN;
    __half* hINK = hIN + (size_t)MT * DMODEL;       // fp16 inK
    __half* hINV = hIN + 2 * (size_t)MT * DMODEL;   // fp16 inV (via stride)
    (void)hINV;
    __half* TT   = (__half*)pTT;
    __half* hQg  = (__half*)pQg;
    __half* hVt  = (__half*)pVt;
    __half* hA   = (__half*)pA;
    float*  S    = (float*)pS;
    float*  P    = (float*)pP;

    cudaFuncSetAttribute(gemm_h<0>,
                         cudaFuncAttributeMaxDynamicSharedMemorySize, GSMEM);
    cudaFuncSetAttribute(gemm_h<1>,
                         cudaFuncAttributeMaxDynamicSharedMemorySize, GSMEM);
    cudaFuncSetAttribute(gemm_h<2>,
                         cudaFuncAttributeMaxDynamicSharedMemorySize, GSMEM);

    const dim3 blk(NT);
    const long long sQK = (long long)SEQ * DMODEL;    // per-batch row-block stride
    const long long sSS = (long long)SEQ * SEQ;       // per-batch scores stride
    const long long sVT = (long long)DMODEL * SEQ;    // per-batch VO^T stride
    const long long sIN = (long long)MT * DMODEL;     // per-matrix input stride
    const long long sW  = (long long)WSZ;             // weight slot stride

    // launch 1: inputs fp32 -> fp16
    const int nBig4 = MT * DMODEL / 4;
    f2h3<<<dim3((nBig4 + 255) / 256, 3), 256>>>(inQ, inK, inV, hIN, nBig4);

    // launch 2: weight prep (3 transposed converts + WO copy)
    prep_w<<<dim3(32, 32, 4), 256>>>(WQ, WK, WV, WO, TT);

    // launch 3: combined small GEMMs (z=0: WVO = WO@WV; z=1: Bqg = WK^T@WQ)
    //   A: TT[0]=WO, TT[1]=WKt (stride +sW); B: TT[2]=WVt, TT[3]=WQt (+sW);
    //   C: TT[4]=WVO, TT[5]=Bqg (+sW), fp16 staged.
    gemm_h<1><<<dim3(DMODEL / BN, DMODEL / BM, 2), blk, GSMEM>>>(
        TT, TT + 2 * sW, TT + 4 * sW, nullptr, nullptr,
        DMODEL, DMODEL, sW, sW, sW);

    // launch 4: batched projections (z=0: Qg = inQ@Bqg^T -> hQg;
    //           z=1: VO = inV@WVO^T -> VO^T side-write into hVt)
    //   A: z0 = hIN (inQ), z1 = hIN+2*sIN (inV); B: z0 = TT[5], z1 = TT[4].
    gemm_h<1><<<dim3(DMODEL / BN, MT / BM, 2), blk, GSMEM>>>(
        hIN, TT + 5 * sW, hQg, nullptr, hVt,
        DMODEL, DMODEL, 2 * sIN, -sW, 0);

    // launch 5: scores = Qg @ inK^T with fused mask+scale -> fp32 (z=0..3)
    gemm_h<2><<<dim3(SEQ / BN, SEQ / BM, NB), blk, GSMEM>>>(
        hQg, hINK, S, mask, nullptr, SEQ, DMODEL, sQK, sQK, sSS);

    // launch 6: softmax (max-free) -> fp16 attn
    softmax_rows<<<NB * SEQ, 256>>>(S, hA);

    // launch 7: P = attn @ VO (NT with B = VO^T) -> fp32 direct
    gemm_h<0><<<dim3(DMODEL / BN, SEQ / BM, NB), blk, GSMEM>>>(
        hA, hVt, P, nullptr, nullptr, DMODEL, SEQ, sSS, sVT, sQK);

    // launch 8: residual + layernorm -> d_out
    add_layernorm<<<MT, 256>>>(P, inQ, gam, bet, out);
}